// round 17
// baseline (speedup 1.0000x reference)
#include <cuda_runtime.h>
#include <math.h>
#include <stdint.h>

#define N_NODES 8192
#define MAXD 128
constexpr int KC = 32;   // encoder GEMM k-chunk

// ---------------- scratch (device globals) ----------------------------------
__device__ __align__(16) float d_msg[N_NODES * 128];
__device__ __align__(16) float d_g  [N_NODES * 128];
__device__ __align__(16) float d_f  [N_NODES * 256];   // [wd(g) | h]
__device__ __align__(16) float d_p1 [N_NODES * 128];
__device__ __align__(16) float d_p2 [N_NODES * 64];
__device__ float d_dinv[N_NODES];
__device__ int   d_cnt [N_NODES];
__device__ int   d_nbr [N_NODES * MAXD];

// transposed weights, [K][M] row-major
__device__ __align__(16) float d_wt1 [32 * 64];
__device__ __align__(16) float d_wt2 [64 * 128];
__device__ __align__(16) float d_wtg [128 * 128];
__device__ __align__(16) float d_wtd [128 * 128];
__device__ __align__(16) float d_wtp1[256 * 128];
__device__ __align__(16) float d_wtp2[128 * 64];

// ---------------- cp.async helpers ------------------------------------------
__device__ __forceinline__ uint32_t smem_u32(const void* p) {
    return (uint32_t)__cvta_generic_to_shared(p);
}
#define CP_ASYNC16(dst_u32, src_ptr) \
    asm volatile("cp.async.cg.shared.global [%0], [%1], 16;" \
                 :: "r"(dst_u32), "l"(src_ptr) : "memory")
#define CP_COMMIT() asm volatile("cp.async.commit_group;" ::: "memory")
#define CP_WAIT0()  asm volatile("cp.async.wait_group 0;"  ::: "memory")

// ---------------- packed f32x2 helpers (PTX-only) ----------------------------
__device__ __forceinline__ unsigned long long f2pack(float lo, float hi) {
    unsigned long long r;
    asm("mov.b64 %0, {%1, %2};" : "=l"(r) : "f"(lo), "f"(hi));
    return r;
}
__device__ __forceinline__ void f2unpack(unsigned long long p, float& lo, float& hi) {
    asm("mov.b64 {%0, %1}, %2;" : "=f"(lo), "=f"(hi) : "l"(p));
}
__device__ __forceinline__ void ffma2(unsigned long long& d,
                                      unsigned long long a, unsigned long long b) {
    asm("fma.rn.f32x2 %0, %1, %2, %0;" : "+l"(d) : "l"(a), "l"(b));
}

// ---------------- weight transpose prep --------------------------------------
__global__ void __launch_bounds__(256)
transpose_weights(const float* __restrict__ w1, const float* __restrict__ w2,
                  const float* __restrict__ wg, const float* __restrict__ wd,
                  const float* __restrict__ wp1, const float* __restrict__ wp2)
{
    const float* Ws[6]  = {w1, w2, wg, wd, wp1, wp2};
    float*       WTs[6] = {d_wt1, d_wt2, d_wtg, d_wtd, d_wtp1, d_wtp2};
    const int    Ms[6]  = {64, 128, 128, 128, 128, 64};
    const int    Ks[6]  = {32, 64, 128, 128, 256, 128};

    int gtid = blockIdx.x * blockDim.x + threadIdx.x;
    int nth  = gridDim.x * blockDim.x;
#pragma unroll
    for (int mi = 0; mi < 6; mi++) {
        int M = Ms[mi], K = Ks[mi], n = M * K;
        const float* W = Ws[mi];
        float* WT = WTs[mi];
        for (int e = gtid; e < n; e += nth) {
            int m = e / K, k = e % K;
            WT[k * M + m] = W[e];
        }
    }
}

// ---------------- per-row adjacency scan (MLP=8 batched loads) ---------------
__device__ __forceinline__ void scan_row(const float* __restrict__ adj, int row)
{
    __shared__ int s_cnt;
    const int tid = threadIdx.x;
    if (tid == 0) s_cnt = 0;
    __syncthreads();

    const float4* a4 = (const float4*)(adj + (size_t)row * N_NODES);
    int* nbr = d_nbr + (size_t)row * MAXD;

    float4 v[8];
#pragma unroll
    for (int u = 0; u < 8; u++)
        v[u] = __ldcs(&a4[tid + u * 256]);

#pragma unroll
    for (int u = 0; u < 8; u++) {
        const int base = (tid + u * 256) * 4;
        if (v[u].x != 0.f) { int p = atomicAdd(&s_cnt, 1); if (p < MAXD) nbr[p] = base + 0; }
        if (v[u].y != 0.f) { int p = atomicAdd(&s_cnt, 1); if (p < MAXD) nbr[p] = base + 1; }
        if (v[u].z != 0.f) { int p = atomicAdd(&s_cnt, 1); if (p < MAXD) nbr[p] = base + 2; }
        if (v[u].w != 0.f) { int p = atomicAdd(&s_cnt, 1); if (p < MAXD) nbr[p] = base + 3; }
    }
    __syncthreads();
    if (tid == 0) {
        int cn = s_cnt;
        d_cnt[row]  = cn < MAXD ? cn : MAXD;
        d_dinv[row] = rsqrtf((float)cn + 1.0f);   // +1 self loop
    }
}

// ---------------- encoder GEMM (256 threads, KC=32 chunks) -------------------
template <int THREADS, int BR, int K, int M, bool RELU>
__device__ __forceinline__ void mlp_gemm(
        const float* in_s, int in_ss,
        const float* __restrict__ WT, const float* __restrict__ bias,
        float* wt_s,
        float* out_s, int out_ss,
        float* out_g, int out_gs, int row0)
{
    constexpr int TX  = M / 4;
    constexpr int TY  = THREADS / TX;
    constexpr int RPT = BR / TY;
    constexpr int CH  = K / KC;
    constexpr int CPB = (KC * M / 4) / THREADS;

    const int tid = threadIdx.x;
    const int tx  = tid % TX;
    const int ty  = tid / TX;

    unsigned long long acc01[RPT], acc23[RPT];
#pragma unroll
    for (int r = 0; r < RPT; r++) { acc01[r] = 0ull; acc23[r] = 0ull; }

    const uint32_t wt_base = smem_u32(wt_s);

    {   // preload chunk 0
        uint32_t dst = wt_base + tid * 16;
        const float* src = WT + tid * 4;
#pragma unroll
        for (int i = 0; i < CPB; i++)
            CP_ASYNC16(dst + i * THREADS * 16, src + i * THREADS * 4);
        CP_COMMIT();
    }

#pragma unroll
    for (int ch = 0; ch < CH; ch++) {
        CP_WAIT0();
        __syncthreads();

        if (ch + 1 < CH) {
            uint32_t dst = wt_base + (uint32_t)(((ch + 1) & 1) * KC * M * 4) + tid * 16;
            const float* src = WT + (size_t)(ch + 1) * KC * M + tid * 4;
#pragma unroll
            for (int i = 0; i < CPB; i++)
                CP_ASYNC16(dst + i * THREADS * 16, src + i * THREADS * 4);
            CP_COMMIT();
        }

        const float* buf = wt_s + (ch & 1) * (KC * M);
        const int k0 = ch * KC;

#pragma unroll
        for (int kv = 0; kv < KC / 4; kv++) {
            unsigned long long w01[4], w23[4];
#pragma unroll
            for (int c = 0; c < 4; c++) {
                float4 w = *(const float4*)&buf[(kv * 4 + c) * M + tx * 4];
                w01[c] = f2pack(w.x, w.y);
                w23[c] = f2pack(w.z, w.w);
            }
#pragma unroll
            for (int rr = 0; rr < RPT; rr++) {
                float4 a = *(const float4*)&in_s[(ty * RPT + rr) * in_ss + k0 + kv * 4];
                unsigned long long aa;
                aa = f2pack(a.x, a.x); ffma2(acc01[rr], aa, w01[0]); ffma2(acc23[rr], aa, w23[0]);
                aa = f2pack(a.y, a.y); ffma2(acc01[rr], aa, w01[1]); ffma2(acc23[rr], aa, w23[1]);
                aa = f2pack(a.z, a.z); ffma2(acc01[rr], aa, w01[2]); ffma2(acc23[rr], aa, w23[2]);
                aa = f2pack(a.w, a.w); ffma2(acc01[rr], aa, w01[3]); ffma2(acc23[rr], aa, w23[3]);
            }
        }
    }

    float4 bb = make_float4(0.f, 0.f, 0.f, 0.f);
    if (bias) bb = *(const float4*)(bias + tx * 4);

#pragma unroll
    for (int rr = 0; rr < RPT; rr++) {
        int r = ty * RPT + rr;
        float4 o;
        f2unpack(acc01[rr], o.x, o.y);
        f2unpack(acc23[rr], o.z, o.w);
        o.x += bb.x; o.y += bb.y; o.z += bb.z; o.w += bb.w;
        if (RELU) {
            o.x = fmaxf(o.x, 0.f); o.y = fmaxf(o.y, 0.f);
            o.z = fmaxf(o.z, 0.f); o.w = fmaxf(o.w, 0.f);
        }
        if (out_s) *(float4*)&out_s[r * out_ss + tx * 4] = o;
        if (out_g) *(float4*)(out_g + (size_t)(row0 + r) * out_gs + tx * 4) = o;
    }
}

// ---------------- fused: encoder blocks (0..255) + scan blocks (256..) ------
__global__ void __launch_bounds__(256, 4)
enc_scan_kernel(const float* __restrict__ x,
                const float* __restrict__ b1, const float* __restrict__ b2,
                float* __restrict__ f, float* __restrict__ msg,
                const float* __restrict__ adj)
{
    if ((int)blockIdx.x >= N_NODES / 32) {
        scan_row(adj, (int)blockIdx.x - N_NODES / 32);
        return;
    }

    extern __shared__ float esm[];
    float* s_a = esm;            // 4096: x tile, later h
    float* s_b = esm + 4096;     // 2048: h1
    float* wt  = esm + 6144;     // 8192: double-buffered weight tiles

    const int tid  = threadIdx.x;
    const int row0 = blockIdx.x * 32;

    {   // load x tile [32,32]
        int r = tid >> 3, vv = tid & 7;
        *(float4*)&s_a[r * 32 + vv * 4] =
            *(const float4*)(x + (size_t)(row0 + r) * 32 + vv * 4);
    }
    __syncthreads();

    mlp_gemm<256, 32, 32, 64, true>(s_a, 32, d_wt1, b1, wt, s_b, 64, nullptr, 0, 0);
    __syncthreads();
    mlp_gemm<256, 32, 64, 128, true>(s_b, 64, d_wt2, b2, wt, s_a, 128, f + 128, 256, row0);
    __syncthreads();
    mlp_gemm<256, 32, 128, 128, false>(s_a, 128, d_wtg, nullptr, wt, nullptr, 0, msg, 128, row0);
}

// ---------------- aggregation: one row per 128-thread block (grid=8192) -----
__global__ void __launch_bounds__(128)
agg_kernel(const float* __restrict__ msg, const float* __restrict__ bg,
           float* __restrict__ g)
{
    const int row = blockIdx.x;
    const int c   = threadIdx.x;

    __shared__ int   s_idx[MAXD];
    __shared__ float s_dj [MAXD];

    const int   cnt = d_cnt[row];
    const float di  = d_dinv[row];

    if (c < cnt) {
        int j = d_nbr[(size_t)row * MAXD + c];
        s_idx[c] = j;
        s_dj[c]  = d_dinv[j];
    }
    __syncthreads();

    float a0 = di * msg[(size_t)row * 128 + c];   // self-loop term
    float a1 = 0.f, a2 = 0.f, a3 = 0.f;
    int k = 0;
    for (; k + 3 < cnt; k += 4) {
        a0 += s_dj[k]     * msg[(size_t)s_idx[k]     * 128 + c];
        a1 += s_dj[k + 1] * msg[(size_t)s_idx[k + 1] * 128 + c];
        a2 += s_dj[k + 2] * msg[(size_t)s_idx[k + 2] * 128 + c];
        a3 += s_dj[k + 3] * msg[(size_t)s_idx[k + 3] * 128 + c];
    }
    for (; k < cnt; k++)
        a0 += s_dj[k] * msg[(size_t)s_idx[k] * 128 + c];

    float v = di * ((a0 + a1) + (a2 + a3)) + bg[c];
    g[(size_t)row * 128 + c] = fmaxf(v, 0.f);
}

// ---------------- big-tile GEMM: 8x8 thread tiles, gmem->gmem ----------------
// OUT[8192, M] = relu(IN[8192, K] @ W^T + b), WT pre-transposed [K][M].
// 128 threads, BR=64 rows/block, thread tile = 8 cols x RPT rows.
// LDS lane-traffic: (8 + RPT) float4 per kv for 32*RPT MACs -> ~1 B/MAC.
template <int K, int M, int MINB>
__global__ void __launch_bounds__(128, MINB)
gemm_big(const float* __restrict__ in_g, int in_gs,
         const float* __restrict__ WT, const float* __restrict__ bias,
         float* __restrict__ out_g, int out_gs)
{
    constexpr int TC  = M / 8;          // thread-cols (each owns 8 cols)
    constexpr int TR  = 128 / TC;       // thread-rows
    constexpr int RPT = 64 / TR;        // rows per thread
    constexpr int KCD = 32;
    constexpr int CH  = K / KCD;
    constexpr int CPB = (KCD * M / 4) / 128;
    constexpr int ISS = K + 4;          // smem input row stride

    extern __shared__ float sm[];
    float* s_in = sm;                   // [64][ISS]
    float* wt_s = sm + 64 * ISS;        // 2*KCD*M double buffer

    const int tid  = threadIdx.x;
    const int tc   = tid % TC;
    const int tr   = tid / TC;
    const int col0 = tc * 8;
    const int row0 = blockIdx.x * 64;

    const uint32_t wt_base = smem_u32(wt_s);

    {   // preload weight chunk 0 (async, overlaps input tile load)
        uint32_t dst = wt_base + tid * 16;
        const float* src = WT + tid * 4;
#pragma unroll
        for (int i = 0; i < CPB; i++)
            CP_ASYNC16(dst + i * 128 * 16, src + i * 128 * 4);
        CP_COMMIT();
    }

    // input tile [64][K] -> smem (coalesced float4)
    for (int idx = tid; idx < 64 * (K / 4); idx += 128) {
        int r = idx / (K / 4), v = idx % (K / 4);
        *(float4*)&s_in[r * ISS + v * 4] =
            *(const float4*)(in_g + (size_t)(row0 + r) * in_gs + v * 4);
    }

    unsigned long long acc[RPT][4];     // RPT rows x 4 col-pairs (8 cols)
#pragma unroll
    for (int i = 0; i < RPT; i++)
#pragma unroll
        for (int c = 0; c < 4; c++) acc[i][c] = 0ull;

#pragma unroll
    for (int ch = 0; ch < CH; ch++) {
        CP_WAIT0();
        __syncthreads();

        if (ch + 1 < CH) {
            uint32_t dst = wt_base + (uint32_t)(((ch + 1) & 1) * KCD * M * 4) + tid * 16;
            const float* src = WT + (size_t)(ch + 1) * KCD * M + tid * 4;
#pragma unroll
            for (int i = 0; i < CPB; i++)
                CP_ASYNC16(dst + i * 128 * 16, src + i * 128 * 4);
            CP_COMMIT();
        }

        const float* buf = wt_s + (ch & 1) * (KCD * M);
        const int k0 = ch * KCD;

#pragma unroll
        for (int kv = 0; kv < KCD / 4; kv++) {
            unsigned long long wp[4][4];   // [k within kv][col-pair]
#pragma unroll
            for (int k = 0; k < 4; k++) {
                float4 wa = *(const float4*)&buf[(kv * 4 + k) * M + col0];
                float4 wb = *(const float4*)&buf[(kv * 4 + k) * M + col0 + 4];
                wp[k][0] = f2pack(wa.x, wa.y);
                wp[k][1] = f2pack(wa.z, wa.w);
                wp[k][2] = f2pack(wb.x, wb.y);
                wp[k][3] = f2pack(wb.z, wb.w);
            }
#pragma unroll
            for (int i = 0; i < RPT; i++) {
                float4 a = *(const float4*)&s_in[(tr * RPT + i) * ISS + k0 + kv * 4];
                unsigned long long aa;
                aa = f2pack(a.x, a.x);
                ffma2(acc[i][0], aa, wp[0][0]); ffma2(acc[i][1], aa, wp[0][1]);
                ffma2(acc[i][2], aa, wp[0][2]); ffma2(acc[i][3], aa, wp[0][3]);
                aa = f2pack(a.y, a.y);
                ffma2(acc[i][0], aa, wp[1][0]); ffma2(acc[i][1], aa, wp[1][1]);
                ffma2(acc[i][2], aa, wp[1][2]); ffma2(acc[i][3], aa, wp[1][3]);
                aa = f2pack(a.z, a.z);
                ffma2(acc[i][0], aa, wp[2][0]); ffma2(acc[i][1], aa, wp[2][1]);
                ffma2(acc[i][2], aa, wp[2][2]); ffma2(acc[i][3], aa, wp[2][3]);
                aa = f2pack(a.w, a.w);
                ffma2(acc[i][0], aa, wp[3][0]); ffma2(acc[i][1], aa, wp[3][1]);
                ffma2(acc[i][2], aa, wp[3][2]); ffma2(acc[i][3], aa, wp[3][3]);
            }
        }
    }

    const float4 b0 = *(const float4*)(bias + col0);
    const float4 b1 = *(const float4*)(bias + col0 + 4);

#pragma unroll
    for (int i = 0; i < RPT; i++) {
        const int r = row0 + tr * RPT + i;
        float4 o0, o1;
        f2unpack(acc[i][0], o0.x, o0.y);
        f2unpack(acc[i][1], o0.z, o0.w);
        f2unpack(acc[i][2], o1.x, o1.y);
        f2unpack(acc[i][3], o1.z, o1.w);
        o0.x = fmaxf(o0.x + b0.x, 0.f); o0.y = fmaxf(o0.y + b0.y, 0.f);
        o0.z = fmaxf(o0.z + b0.z, 0.f); o0.w = fmaxf(o0.w + b0.w, 0.f);
        o1.x = fmaxf(o1.x + b1.x, 0.f); o1.y = fmaxf(o1.y + b1.y, 0.f);
        o1.z = fmaxf(o1.z + b1.z, 0.f); o1.w = fmaxf(o1.w + b1.w, 0.f);
        *(float4*)(out_g + (size_t)r * out_gs + col0)     = o0;
        *(float4*)(out_g + (size_t)r * out_gs + col0 + 4) = o1;
    }
}

// ---------------- final small GEMM (M=8) + mask -------------------------------
__global__ void __launch_bounds__(256)
out_kernel(const float* __restrict__ q,   // [N,64]
           const float* __restrict__ wo,  // [8,64]
           const float* __restrict__ bo,  // [8]
           const float* __restrict__ mask,
           float* __restrict__ out)       // [N,8]
{
    __shared__ float q_sh[32][65];
    __shared__ float wo_sh[8][65];
    __shared__ float bo_sh[8];

    const int tid  = threadIdx.x;
    const int row0 = blockIdx.x * 32;

    for (int i = tid; i < 32 * 64; i += 256) {
        int r = i / 64, k = i % 64;
        q_sh[r][k] = q[(size_t)(row0 + r) * 64 + k];
    }
    for (int i = tid; i < 8 * 64; i += 256)
        wo_sh[i / 64][i % 64] = wo[i];
    if (tid < 8) bo_sh[tid] = bo[tid];
    __syncthreads();

    const int r = tid / 8, m = tid % 8;
    float acc = 0.f;
#pragma unroll
    for (int k = 0; k < 64; k++) acc += q_sh[r][k] * wo_sh[m][k];

    out[(size_t)(row0 + r) * 8 + m] = (acc + bo_sh[m]) * mask[row0 + r];
}

// ---------------- launch -----------------------------------------------------
extern "C" void kernel_launch(void* const* d_in, const int* in_sizes, int n_in,
                              void* d_out, int out_size)
{
    const float* x    = (const float*)d_in[0];
    const float* adj  = (const float*)d_in[1];
    const float* mask = (const float*)d_in[2];
    const float* w1   = (const float*)d_in[3];
    const float* b1   = (const float*)d_in[4];
    const float* w2   = (const float*)d_in[5];
    const float* b2   = (const float*)d_in[6];
    const float* wg   = (const float*)d_in[7];
    const float* bg   = (const float*)d_in[8];
    const float* wd   = (const float*)d_in[9];
    const float* bd   = (const float*)d_in[10];
    const float* wp1  = (const float*)d_in[11];
    const float* bp1  = (const float*)d_in[12];
    const float* wp2  = (const float*)d_in[13];
    const float* bp2  = (const float*)d_in[14];
    const float* wo   = (const float*)d_in[15];
    const float* bo   = (const float*)d_in[16];
    float* out = (float*)d_out;

    float *p_msg, *p_f, *p_g, *p_p1, *p_p2;
    float *p_wtd, *p_wtp1, *p_wtp2;
    cudaGetSymbolAddress((void**)&p_msg,  d_msg);
    cudaGetSymbolAddress((void**)&p_f,    d_f);
    cudaGetSymbolAddress((void**)&p_g,    d_g);
    cudaGetSymbolAddress((void**)&p_p1,   d_p1);
    cudaGetSymbolAddress((void**)&p_p2,   d_p2);
    cudaGetSymbolAddress((void**)&p_wtd,  d_wtd);   // REAL device addresses —
    cudaGetSymbolAddress((void**)&p_wtp1, d_wtp1);  // passing the __device__
    cudaGetSymbolAddress((void**)&p_wtp2, d_wtp2);  // symbol gave the host
                                                    // shadow (read as zeros
                                                    // via ATS) in R16.

    const int ENC_SMEM = (4096 + 2048 + 8192) * 4;             // 57344 B
    const int WD_SMEM  = (64 * 132 + 2 * 32 * 128) * 4;        // 66560 B
    const int WP1_SMEM = (64 * 260 + 2 * 32 * 128) * 4;        // 99328 B
    const int WP2_SMEM = (64 * 132 + 2 * 32 * 64) * 4;         // 50176 B
    static int smem_set = 0;
    if (!smem_set) {
        cudaFuncSetAttribute(enc_scan_kernel,
                             cudaFuncAttributeMaxDynamicSharedMemorySize, ENC_SMEM);
        cudaFuncSetAttribute(gemm_big<128, 128, 3>,
                             cudaFuncAttributeMaxDynamicSharedMemorySize, WD_SMEM);
        cudaFuncSetAttribute(gemm_big<256, 128, 2>,
                             cudaFuncAttributeMaxDynamicSharedMemorySize, WP1_SMEM);
        cudaFuncSetAttribute(gemm_big<128, 64, 4>,
                             cudaFuncAttributeMaxDynamicSharedMemorySize, WP2_SMEM);
        smem_set = 1;
    }

    transpose_weights<<<128, 256>>>(w1, w2, wg, wd, wp1, wp2);
    enc_scan_kernel<<<N_NODES / 32 + N_NODES, 256, ENC_SMEM>>>(
        x, b1, b2, p_f, p_msg, adj);
    agg_kernel<<<N_NODES, 128>>>(p_msg, bg, p_g);

    // decoder chain: three big-tile GEMMs (gmem->gmem), then masked output
    gemm_big<128, 128, 3><<<N_NODES / 64, 128, WD_SMEM>>>(
        p_g, 128, p_wtd, bd, p_f, 256);          // d -> f[:,0:128]
    gemm_big<256, 128, 2><<<N_NODES / 64, 128, WP1_SMEM>>>(
        p_f, 256, p_wtp1, bp1, p_p1, 128);       // p1
    gemm_big<128, 64, 4><<<N_NODES / 64, 128, WP2_SMEM>>>(
        p_p1, 128, p_wtp2, bp2, p_p2, 64);       // p2
    out_kernel<<<N_NODES / 32, 256>>>(p_p2, wo, bo, mask, out);
}